// round 16
// baseline (speedup 1.0000x reference)
#include <cuda_runtime.h>
#include <cuda_fp16.h>
#include <cstdint>
#include <math.h>

#define Bn 32
#define Sn 2048
#define En 1024
#define Hn 1024

// -------------------- device scratch (no cudaMalloc allowed) ----------------
__device__ __half g_ench[(size_t)Bn * Sn * En];  // fp16 of gathered (unmasked) enc
__device__ __half g_mwh[Hn * En];                // fp16 of M_w[:, :E]
__device__ float g_colpart[32][Hn];              // partial colsums of M_w[:, E:]
__device__ float g_scores[Bn * Sn];              // compacted scores
__device__ float g_wc[Bn * Sn];                  // compacted weights
__device__ int   g_sidx[Bn * Sn];                // j -> s mapping per batch
__device__ int   g_cnt[Bn];                      // unmasked count per batch

// -------------------- helpers ------------------------------------------------
__device__ __forceinline__ uint32_t smem_u32(const void* p) {
    return (uint32_t)__cvta_generic_to_shared(const_cast<void*>(p));
}
__device__ __forceinline__ void cpasync16(uint32_t dst, const void* src) {
    asm volatile("cp.async.cg.shared.global [%0], [%1], 16;" :: "r"(dst), "l"(src));
}
#define CP_COMMIT() asm volatile("cp.async.commit_group;" ::: "memory")
#define CP_WAIT(n)  asm volatile("cp.async.wait_group %0;" :: "n"(n) : "memory")

__device__ __forceinline__ void ldsm4(uint32_t* r, uint32_t addr) {
    asm volatile("ldmatrix.sync.aligned.m8n8.x4.shared.b16 {%0,%1,%2,%3}, [%4];"
                 : "=r"(r[0]), "=r"(r[1]), "=r"(r[2]), "=r"(r[3]) : "r"(addr));
}
__device__ __forceinline__ void mma_16816(float* c, const uint32_t* a, const uint32_t* b) {
    asm volatile(
        "mma.sync.aligned.m16n8k16.row.col.f32.f16.f16.f32 "
        "{%0,%1,%2,%3}, {%4,%5,%6,%7}, {%8,%9}, {%0,%1,%2,%3};"
        : "+f"(c[0]), "+f"(c[1]), "+f"(c[2]), "+f"(c[3])
        : "r"(a[0]), "r"(a[1]), "r"(a[2]), "r"(a[3]), "r"(b[0]), "r"(b[1]));
}
__device__ __forceinline__ float tanh_fast(float x) {
    float e;
    asm("ex2.approx.f32 %0, %1;" : "=f"(e) : "f"(x * 2.885390082f));
    float r;
    asm("rcp.approx.f32 %0, %1;" : "=f"(r) : "f"(e + 1.0f));
    return fmaf(-2.0f, r, 1.0f);
}
#define SW128(o) ((o) ^ ((((uint32_t)(o)) >> 3) & 0x70u))

// -------------------- fused prep kernels -------------------------------------
__global__ void init_index_kernel(const int* __restrict__ mask,
                                  float* __restrict__ out_all) {
    const int b = blockIdx.x;
    const int tid = threadIdx.x;
    const int gid = b * 256 + tid;           // 8192 global threads

    for (int i = gid; i < Bn * En + Bn * Sn; i += 8192) out_all[i] = 0.0f;
    for (int i = gid; i < Bn * Sn; i += 8192) g_scores[i] = 0.0f;

    __shared__ int ssum[256];
    int keep[8];
    int loc = 0;
#pragma unroll
    for (int i = 0; i < 8; ++i) {
        const int s = tid * 8 + i;
        keep[i] = (mask[b * Sn + s] == 0) ? 1 : 0;
        loc += keep[i];
    }
    ssum[tid] = loc;
    __syncthreads();
    for (int off = 1; off < 256; off <<= 1) {
        int v = (tid >= off) ? ssum[tid - off] : 0;
        __syncthreads();
        ssum[tid] += v;
        __syncthreads();
    }
    int base = ssum[tid] - loc;
#pragma unroll
    for (int i = 0; i < 8; ++i) {
        if (keep[i]) g_sidx[b * Sn + base++] = tid * 8 + i;
    }
    if (tid == 255) g_cnt[b] = ssum[255];
}

__global__ void prep_mw_kernel(const float* __restrict__ Mw) {
    const int r = blockIdx.x;
    const int g0 = r * 32;

    {
        const int h4 = threadIdx.x * 4;
        float4 acc = make_float4(0.f, 0.f, 0.f, 0.f);
#pragma unroll 4
        for (int g = 0; g < 32; ++g) {
            const float4 v = *(const float4*)(Mw + (size_t)(g0 + g) * (En + Hn) + En + h4);
            acc.x += v.x; acc.y += v.y; acc.z += v.z; acc.w += v.w;
        }
        *(float4*)&g_colpart[r][h4] = acc;
    }

    for (int i = threadIdx.x; i < 32 * 256; i += 256) {
        const int lr = i >> 8;
        const int e4 = (i & 255) * 4;
        const float4 v = *(const float4*)(Mw + (size_t)(g0 + lr) * (En + Hn) + e4);
        __half* d = g_mwh + (size_t)(g0 + lr) * En + e4;
        *(__half2*)d       = __floats2half2_rn(v.x, v.y);
        *(__half2*)(d + 2) = __floats2half2_rn(v.z, v.w);
    }
}

__global__ void encgather_kernel(const float* __restrict__ enc) {
    const int b = blockIdx.y;
    const int cnt = g_cnt[b];
    const int pad = (cnt + 127) & ~127;
    const int j = blockIdx.x * 8 + (threadIdx.x >> 5);
    if (j >= pad) return;
    const int lane = threadIdx.x & 31;
    __half* dst = g_ench + (size_t)b * Sn * En + (size_t)j * En;

    if (j < cnt) {
        const int s = g_sidx[b * Sn + j];
        const float* src = enc + (size_t)b * Sn * En + (size_t)s * En;
#pragma unroll
        for (int i = 0; i < 8; ++i) {
            const int c4 = (lane + i * 32) * 4;
            const float4 v = *(const float4*)(src + c4);
            *(__half2*)(dst + c4)     = __floats2half2_rn(v.x, v.y);
            *(__half2*)(dst + c4 + 2) = __floats2half2_rn(v.z, v.w);
        }
    } else {
#pragma unroll
        for (int i = 0; i < 8; ++i) {
            const int c4 = (lane + i * 32) * 4;
            *(__half2*)(dst + c4)     = __half2(__float2half(0.f), __float2half(0.f));
            *(__half2*)(dst + c4 + 2) = __half2(__float2half(0.f), __float2half(0.f));
        }
    }
}

// -------------------- mma.sync fused scores kernel ---------------------------
// BN=64 tiles: warp tile 32x32 -> 32 accum regs/thread -> 3 CTAs/SM (occ 36%)
// to cover the ldsm->mma RAW latency that capped tensor util at 47.7%.
// 3-stage cp.async pipeline, one barrier per iteration.
#define BM 128
#define BN 64
#define BK 64
#define NT (Hn / BN)        // 16
#define KT (En / BK)        // 16
#define MT (Sn / BM)        // 16
#define A_BYTES 16384
#define B_BYTES 8192
#define STAGE_BYTES (A_BYTES + B_BYTES)   // 24576
#define NSTAGE 3
#define T_A 0
#define T_B A_BYTES
#define OFF_VW  (NSTAGE * STAGE_BYTES)    // 73728
#define OFF_HC  (OFF_VW + 256)
#define SMEM_SC (OFF_HC + 256)

__device__ __forceinline__ void load_stage(uint32_t sb, int stage, int nt, int kt,
                                           size_t m0, int tid) {
    const uint32_t sbase = sb + stage * STAGE_BYTES;
    // A: 128 rows x 128B; 2 threads/row, 64B each (4x16B)
    {
        const int r  = tid >> 1;
        const int cb = (tid & 1) * 64;
        const char* a = (const char*)(g_ench + (m0 + r) * En + kt * BK) + cb;
        const uint32_t soff = (uint32_t)(r * 128 + cb);
#pragma unroll
        for (int i = 0; i < 4; ++i)
            cpasync16(sbase + T_A + SW128(soff + i * 16), a + i * 16);
    }
    // B: 64 rows x 128B; 4 threads/row, 32B each (2x16B)
    {
        const int r  = tid >> 2;
        const int cb = (tid & 3) * 32;
        const char* b = (const char*)(g_mwh + (size_t)(nt * BN + r) * En + kt * BK) + cb;
        const uint32_t soff = (uint32_t)(r * 128 + cb);
#pragma unroll
        for (int i = 0; i < 2; ++i)
            cpasync16(sbase + T_B + SW128(soff + i * 16), b + i * 16);
    }
}

__global__ __launch_bounds__(256, 3)
void scores_mma_kernel(const float* __restrict__ hidden,
                       const float* __restrict__ Mb,
                       const float* __restrict__ Vw) {
    const int uid = blockIdx.x;
    const int nt = uid & (NT - 1);
    const int mt = (uid >> 4) & (MT - 1);
    const int b  = uid >> 8;

    const int pad = (g_cnt[b] + 127) & ~127;
    if (mt * BM >= pad) return;

    extern __shared__ char smem[];
    const uint32_t sb = smem_u32(smem);
    const int tid = threadIdx.x, wid = tid >> 5, lid = tid & 31;
    const int wm = wid & 3, wn = wid >> 2;   // 4m x 2n warps, warp tile 32x32
    const size_t m0 = (size_t)b * Sn + mt * BM;
    const int n0 = nt * BN;

    float* s_vw = (float*)(smem + OFF_VW);
    float* s_hc = (float*)(smem + OFF_HC);
    if (tid < BN) {
        float cs = 0.0f;
#pragma unroll
        for (int p = 0; p < 32; ++p) cs += g_colpart[p][n0 + tid];
        s_vw[tid] = Vw[n0 + tid];
        s_hc[tid] = fmaf(hidden[b * Hn + n0 + tid], cs, Mb[n0 + tid]);
    }

    const int a_row = wm * 32 + (lid & 15);
    const int a_kb  = (lid >> 4) * 16;
    const int b_row = wn * 32 + (lid & 7) + ((lid >> 4) << 3);
    const int b_kb  = ((lid >> 3) & 1) * 16;

    float c[2][4][4];
#pragma unroll
    for (int mi = 0; mi < 2; ++mi)
#pragma unroll
        for (int j = 0; j < 4; ++j)
#pragma unroll
            for (int v = 0; v < 4; ++v) c[mi][j][v] = 0.0f;

    load_stage(sb, 0, nt, 0, m0, tid);
    CP_COMMIT();
    load_stage(sb, 1, nt, 1, m0, tid);
    CP_COMMIT();

    int stage = 0;
    for (int t = 0; t < KT; ++t) {
        if (t + 1 < KT) { CP_WAIT(1); } else { CP_WAIT(0); }
        __syncthreads();

        if (t + 2 < KT) {
            load_stage(sb, (stage + 2) % NSTAGE, nt, t + 2, m0, tid);
            CP_COMMIT();
        }

        const uint32_t sbase = sb + stage * STAGE_BYTES;
#pragma unroll
        for (int ks = 0; ks < 4; ++ks) {
            const int kb = ks * 32;
            uint32_t ah[2][4], bh[2][4];
#pragma unroll
            for (int mi = 0; mi < 2; ++mi) {
                const uint32_t ao = SW128((uint32_t)((a_row + mi * 16) * 128 + a_kb + kb));
                ldsm4(ah[mi], sbase + T_A + ao);
            }
#pragma unroll
            for (int q = 0; q < 2; ++q) {
                const uint32_t bo = SW128((uint32_t)((b_row + q * 16) * 128 + b_kb + kb));
                ldsm4(bh[q], sbase + T_B + bo);
            }
#pragma unroll
            for (int mi = 0; mi < 2; ++mi)
#pragma unroll
                for (int q = 0; q < 2; ++q) {
                    mma_16816(c[mi][2 * q],     ah[mi], &bh[q][0]);
                    mma_16816(c[mi][2 * q + 1], ah[mi], &bh[q][2]);
                }
        }
        stage = (stage + 1 == NSTAGE) ? 0 : stage + 1;
    }

    // epilogue: tanh + V-weighted partial rowsum for this 64-wide n-tile
    float rs[4] = {0.f, 0.f, 0.f, 0.f};
    const int nb = wn * 32 + (lid & 3) * 2;
#pragma unroll
    for (int mi = 0; mi < 2; ++mi)
#pragma unroll
        for (int j = 0; j < 4; ++j) {
            const int n = nb + j * 8;
            const float hc0 = s_hc[n],     vw0 = s_vw[n];
            const float hc1 = s_hc[n + 1], vw1 = s_vw[n + 1];
            float* cc = c[mi][j];
            rs[mi * 2 + 0] = fmaf(tanh_fast(cc[0] + hc0), vw0,
                             fmaf(tanh_fast(cc[1] + hc1), vw1, rs[mi * 2 + 0]));
            rs[mi * 2 + 1] = fmaf(tanh_fast(cc[2] + hc0), vw0,
                             fmaf(tanh_fast(cc[3] + hc1), vw1, rs[mi * 2 + 1]));
        }

#pragma unroll
    for (int i = 0; i < 4; ++i) {
        rs[i] += __shfl_xor_sync(0xffffffffu, rs[i], 1);
        rs[i] += __shfl_xor_sync(0xffffffffu, rs[i], 2);
    }
    if ((lid & 3) == 0) {
        const size_t r0 = m0 + wm * 32 + (lid >> 2);
        atomicAdd(&g_scores[r0],      rs[0]);
        atomicAdd(&g_scores[r0 + 8],  rs[1]);
        atomicAdd(&g_scores[r0 + 16], rs[2]);
        atomicAdd(&g_scores[r0 + 24], rs[3]);
    }
}

// -------------------- softmax over compacted scores + scatter ----------------
__global__ void softmax_kernel(float* __restrict__ weights) {
    const int b = blockIdx.x;
    const int tid = threadIdx.x;
    const int cnt = g_cnt[b];
    __shared__ float red[256];

    float vals[8];
    float mx = -INFINITY;
#pragma unroll
    for (int i = 0; i < 8; ++i) {
        const int j = tid + i * 256;
        vals[i] = (j < cnt) ? g_scores[b * Sn + j] : -INFINITY;
        mx = fmaxf(mx, vals[i]);
    }
    red[tid] = mx;
    __syncthreads();
    for (int o = 128; o; o >>= 1) {
        if (tid < o) red[tid] = fmaxf(red[tid], red[tid + o]);
        __syncthreads();
    }
    mx = red[0];
    __syncthreads();

    float sum = 0.f;
#pragma unroll
    for (int i = 0; i < 8; ++i) {
        vals[i] = __expf(vals[i] - mx);
        sum += vals[i];
    }
    red[tid] = sum;
    __syncthreads();
    for (int o = 128; o; o >>= 1) {
        if (tid < o) red[tid] += red[tid + o];
        __syncthreads();
    }
    const float inv = 1.0f / red[0];
#pragma unroll
    for (int i = 0; i < 8; ++i) {
        const int j = tid + i * 256;
        if (j < cnt) {
            const float w = vals[i] * inv;
            g_wc[b * Sn + j] = w;
            weights[b * Sn + g_sidx[b * Sn + j]] = w;
        }
    }
}

// -------------------- weighted sum from compact fp16 enc ---------------------
__global__ void weighted_kernel(float* __restrict__ out) {
    const int b = blockIdx.y;
    const int cnt = g_cnt[b];
    const int j0 = blockIdx.z * 256;
    if (j0 >= cnt) return;
    const int e2 = blockIdx.x * 256 + threadIdx.x;

    __shared__ float w[256];
    const int j = j0 + threadIdx.x;
    w[threadIdx.x] = (j < cnt) ? g_wc[b * Sn + j] : 0.0f;
    __syncthreads();

    const __half2* ebase =
        (const __half2*)(g_ench + (size_t)b * Sn * En + (size_t)j0 * En) + e2;
    const int lim = min(256, cnt - j0);
    float ax = 0.f, ay = 0.f;
    for (int t = 0; t < lim; ++t) {
        const float2 v = __half22float2(ebase[(size_t)t * (En / 2)]);
        ax = fmaf(w[t], v.x, ax);
        ay = fmaf(w[t], v.y, ay);
    }
    atomicAdd(&out[b * En + 2 * e2],     ax);
    atomicAdd(&out[b * En + 2 * e2 + 1], ay);
}

// -----------------------------------------------------------------------------
extern "C" void kernel_launch(void* const* d_in, const int* in_sizes, int n_in,
                              void* d_out, int out_size) {
    const float* hidden = (const float*)d_in[0];
    const float* enc    = (const float*)d_in[1];
    const int*   mask   = (const int*)d_in[2];
    const float* Mw     = (const float*)d_in[3];
    const float* Mb     = (const float*)d_in[4];
    const float* Vw     = (const float*)d_in[5];

    float* out_all      = (float*)d_out;
    float* out_weights  = (float*)d_out + Bn * En;

    cudaFuncSetAttribute(scores_mma_kernel,
                         cudaFuncAttributeMaxDynamicSharedMemorySize, SMEM_SC);

    prep_mw_kernel<<<32, 256>>>(Mw);
    init_index_kernel<<<Bn, 256>>>(mask, out_all);

    dim3 ggrid(Sn / 8, Bn);
    encgather_kernel<<<ggrid, 256>>>(enc);

    scores_mma_kernel<<<Bn * MT * NT, 256, SMEM_SC>>>(hidden, Mb, Vw);

    softmax_kernel<<<Bn, 256>>>(out_weights);

    dim3 wgrid(En / 512, Bn, Sn / 256);
    weighted_kernel<<<wgrid, 256>>>(out_all);
}

// round 17
// speedup vs baseline: 1.1152x; 1.1152x over previous
#include <cuda_runtime.h>
#include <cuda_fp16.h>
#include <cstdint>
#include <math.h>

#define Bn 32
#define Sn 2048
#define En 1024
#define Hn 1024

// -------------------- device scratch (no cudaMalloc allowed) ----------------
__device__ __half g_ench[(size_t)Bn * Sn * En];  // fp16 of gathered (unmasked) enc
__device__ __half g_mwh[Hn * En];                // fp16 of M_w[:, :E]
__device__ float g_colpart[32][Hn];              // partial colsums of M_w[:, E:]
__device__ float g_scores[Bn * Sn];              // compacted scores
__device__ float g_wc[Bn * Sn];                  // compacted weights
__device__ int   g_sidx[Bn * Sn];                // j -> s mapping per batch
__device__ int   g_cnt[Bn];                      // unmasked count per batch

// -------------------- helpers ------------------------------------------------
__device__ __forceinline__ uint32_t smem_u32(const void* p) {
    return (uint32_t)__cvta_generic_to_shared(const_cast<void*>(p));
}
__device__ __forceinline__ void cpasync16(uint32_t dst, const void* src) {
    asm volatile("cp.async.cg.shared.global [%0], [%1], 16;" :: "r"(dst), "l"(src));
}
#define CP_COMMIT() asm volatile("cp.async.commit_group;" ::: "memory")
#define CP_WAIT(n)  asm volatile("cp.async.wait_group %0;" :: "n"(n) : "memory")

__device__ __forceinline__ void ldsm4(uint32_t* r, uint32_t addr) {
    asm volatile("ldmatrix.sync.aligned.m8n8.x4.shared.b16 {%0,%1,%2,%3}, [%4];"
                 : "=r"(r[0]), "=r"(r[1]), "=r"(r[2]), "=r"(r[3]) : "r"(addr));
}
__device__ __forceinline__ void mma_16816(float* c, const uint32_t* a, const uint32_t* b) {
    asm volatile(
        "mma.sync.aligned.m16n8k16.row.col.f32.f16.f16.f32 "
        "{%0,%1,%2,%3}, {%4,%5,%6,%7}, {%8,%9}, {%0,%1,%2,%3};"
        : "+f"(c[0]), "+f"(c[1]), "+f"(c[2]), "+f"(c[3])
        : "r"(a[0]), "r"(a[1]), "r"(a[2]), "r"(a[3]), "r"(b[0]), "r"(b[1]));
}
__device__ __forceinline__ float tanh_fast(float x) {
    float e;
    asm("ex2.approx.f32 %0, %1;" : "=f"(e) : "f"(x * 2.885390082f));
    float r;
    asm("rcp.approx.f32 %0, %1;" : "=f"(r) : "f"(e + 1.0f));
    return fmaf(-2.0f, r, 1.0f);
}
#define SW128(o) ((o) ^ ((((uint32_t)(o)) >> 3) & 0x70u))

// -------------------- fused prep: Mw prep (blocks 0-31) + zero/index (32-63) --
__global__ void prep_all_kernel(const float* __restrict__ Mw,
                                const int* __restrict__ mask,
                                float* __restrict__ out_all) {
    const int tid = threadIdx.x;
    if (blockIdx.x < 32) {
        // ---- Mw prep: colsum partials + fp16 convert for rows [32r, 32r+32)
        const int r = blockIdx.x;
        const int g0 = r * 32;
        {
            const int h4 = tid * 4;
            float4 acc = make_float4(0.f, 0.f, 0.f, 0.f);
#pragma unroll 4
            for (int g = 0; g < 32; ++g) {
                const float4 v = *(const float4*)(Mw + (size_t)(g0 + g) * (En + Hn) + En + h4);
                acc.x += v.x; acc.y += v.y; acc.z += v.z; acc.w += v.w;
            }
            *(float4*)&g_colpart[r][h4] = acc;
        }
        for (int i = tid; i < 32 * 256; i += 256) {
            const int lr = i >> 8;
            const int e4 = (i & 255) * 4;
            const float4 v = *(const float4*)(Mw + (size_t)(g0 + lr) * (En + Hn) + e4);
            __half* d = g_mwh + (size_t)(g0 + lr) * En + e4;
            *(__half2*)d       = __floats2half2_rn(v.x, v.y);
            *(__half2*)(d + 2) = __floats2half2_rn(v.z, v.w);
        }
    } else {
        // ---- zero output + scores scratch, then per-batch mask compaction
        const int b = blockIdx.x - 32;
        const int gid = b * 256 + tid;       // 8192 threads total

        for (int i = gid; i < Bn * En + Bn * Sn; i += 8192) out_all[i] = 0.0f;
        for (int i = gid; i < Bn * Sn; i += 8192) g_scores[i] = 0.0f;

        __shared__ int ssum[256];
        int keep[8];
        int loc = 0;
#pragma unroll
        for (int i = 0; i < 8; ++i) {
            const int s = tid * 8 + i;
            keep[i] = (mask[b * Sn + s] == 0) ? 1 : 0;
            loc += keep[i];
        }
        ssum[tid] = loc;
        __syncthreads();
        for (int off = 1; off < 256; off <<= 1) {
            int v = (tid >= off) ? ssum[tid - off] : 0;
            __syncthreads();
            ssum[tid] += v;
            __syncthreads();
        }
        int base = ssum[tid] - loc;
#pragma unroll
        for (int i = 0; i < 8; ++i) {
            if (keep[i]) g_sidx[b * Sn + base++] = tid * 8 + i;
        }
        if (tid == 255) g_cnt[b] = ssum[255];
    }
}

// gather + fp32->fp16 of unmasked enc rows
__global__ void encgather_kernel(const float* __restrict__ enc) {
    const int b = blockIdx.y;
    const int cnt = g_cnt[b];
    const int pad = (cnt + 127) & ~127;
    const int j = blockIdx.x * 8 + (threadIdx.x >> 5);
    if (j >= pad) return;
    const int lane = threadIdx.x & 31;
    __half* dst = g_ench + (size_t)b * Sn * En + (size_t)j * En;

    if (j < cnt) {
        const int s = g_sidx[b * Sn + j];
        const float* src = enc + (size_t)b * Sn * En + (size_t)s * En;
#pragma unroll
        for (int i = 0; i < 8; ++i) {
            const int c4 = (lane + i * 32) * 4;
            const float4 v = *(const float4*)(src + c4);
            *(__half2*)(dst + c4)     = __floats2half2_rn(v.x, v.y);
            *(__half2*)(dst + c4 + 2) = __floats2half2_rn(v.z, v.w);
        }
    } else {
#pragma unroll
        for (int i = 0; i < 8; ++i) {
            const int c4 = (lane + i * 32) * 4;
            *(__half2*)(dst + c4)     = __half2(__float2half(0.f), __float2half(0.f));
            *(__half2*)(dst + c4 + 2) = __half2(__float2half(0.f), __float2half(0.f));
        }
    }
}

// -------------------- mma.sync fused scores kernel (R15 config) --------------
// BM=128, BN=128, occ 2, 3-stage cp.async pipeline, one barrier per iteration.
#define BM 128
#define BN 128
#define BK 64
#define NT (Hn / BN)        // 8
#define KT (En / BK)        // 16
#define MT (Sn / BM)        // 16
#define STAGE_BYTES 32768
#define NSTAGE 3
#define T_A 0
#define T_B 16384
#define OFF_VW  (NSTAGE * STAGE_BYTES)
#define OFF_HC  (OFF_VW + 512)
#define SMEM_SC (OFF_HC + 512)

__device__ __forceinline__ void load_stage(uint32_t sb, int stage, int nt, int kt,
                                           size_t m0, int tid) {
    const int r  = tid >> 1;
    const int cb = (tid & 1) * 64;
    const uint32_t sbase = sb + stage * STAGE_BYTES;
    const uint32_t soff = (uint32_t)(r * 128 + cb);
    const char* a = (const char*)(g_ench + (m0 + r) * En + kt * BK) + cb;
    const char* b = (const char*)(g_mwh + (size_t)(nt * BN + r) * En + kt * BK) + cb;
#pragma unroll
    for (int i = 0; i < 4; ++i) {
        const uint32_t d = SW128(soff + i * 16);
        cpasync16(sbase + T_A + d, a + i * 16);
        cpasync16(sbase + T_B + d, b + i * 16);
    }
}

__global__ __launch_bounds__(256, 2)
void scores_mma_kernel(const float* __restrict__ hidden,
                       const float* __restrict__ Mb,
                       const float* __restrict__ Vw) {
    const int uid = blockIdx.x;
    const int nt = uid & (NT - 1);
    const int mt = (uid >> 3) & (MT - 1);
    const int b  = uid >> 7;

    const int pad = (g_cnt[b] + 127) & ~127;
    if (mt * BM >= pad) return;

    extern __shared__ char smem[];
    const uint32_t sb = smem_u32(smem);
    const int tid = threadIdx.x, wid = tid >> 5, lid = tid & 31;
    const int wm = wid & 3, wn = wid >> 2;
    const size_t m0 = (size_t)b * Sn + mt * BM;
    const int n0 = nt * BN;

    float* s_vw = (float*)(smem + OFF_VW);
    float* s_hc = (float*)(smem + OFF_HC);
    if (tid < 128) {
        float cs = 0.0f;
#pragma unroll
        for (int p = 0; p < 32; ++p) cs += g_colpart[p][n0 + tid];
        s_vw[tid] = Vw[n0 + tid];
        s_hc[tid] = fmaf(hidden[b * Hn + n0 + tid], cs, Mb[n0 + tid]);
    }

    const int a_row = wm * 32 + (lid & 15);
    const int a_kb  = (lid >> 4) * 16;
    const int b_row = wn * 64 + (lid & 7) + ((lid >> 4) << 3);
    const int b_kb  = ((lid >> 3) & 1) * 16;

    float c[2][8][4];
#pragma unroll
    for (int mi = 0; mi < 2; ++mi)
#pragma unroll
        for (int j = 0; j < 8; ++j)
#pragma unroll
            for (int v = 0; v < 4; ++v) c[mi][j][v] = 0.0f;

    load_stage(sb, 0, nt, 0, m0, tid);
    CP_COMMIT();
    load_stage(sb, 1, nt, 1, m0, tid);
    CP_COMMIT();

    int stage = 0;
    for (int t = 0; t < KT; ++t) {
        if (t + 1 < KT) { CP_WAIT(1); } else { CP_WAIT(0); }
        __syncthreads();

        if (t + 2 < KT) {
            load_stage(sb, (stage + 2) % NSTAGE, nt, t + 2, m0, tid);
            CP_COMMIT();
        }

        const uint32_t sbase = sb + stage * STAGE_BYTES;
#pragma unroll
        for (int ks = 0; ks < 4; ++ks) {
            const int kb = ks * 32;
            uint32_t ah[2][4], bh[4][4];
#pragma unroll
            for (int mi = 0; mi < 2; ++mi) {
                const uint32_t ao = SW128((uint32_t)((a_row + mi * 16) * 128 + a_kb + kb));
                ldsm4(ah[mi], sbase + T_A + ao);
            }
#pragma unroll
            for (int q = 0; q < 4; ++q) {
                const uint32_t bo = SW128((uint32_t)((b_row + q * 16) * 128 + b_kb + kb));
                ldsm4(bh[q], sbase + T_B + bo);
            }
#pragma unroll
            for (int mi = 0; mi < 2; ++mi)
#pragma unroll
                for (int q = 0; q < 4; ++q) {
                    mma_16816(c[mi][2 * q],     ah[mi], &bh[q][0]);
                    mma_16816(c[mi][2 * q + 1], ah[mi], &bh[q][2]);
                }
        }
        stage = (stage + 1 == NSTAGE) ? 0 : stage + 1;
    }

    // epilogue: tanh + V-weighted partial rowsum
    float rs[4] = {0.f, 0.f, 0.f, 0.f};
    const int nb = wn * 64 + (lid & 3) * 2;
#pragma unroll
    for (int mi = 0; mi < 2; ++mi)
#pragma unroll
        for (int j = 0; j < 8; ++j) {
            const int n = nb + j * 8;
            const float hc0 = s_hc[n],     vw0 = s_vw[n];
            const float hc1 = s_hc[n + 1], vw1 = s_vw[n + 1];
            float* cc = c[mi][j];
            rs[mi * 2 + 0] = fmaf(tanh_fast(cc[0] + hc0), vw0,
                             fmaf(tanh_fast(cc[1] + hc1), vw1, rs[mi * 2 + 0]));
            rs[mi * 2 + 1] = fmaf(tanh_fast(cc[2] + hc0), vw0,
                             fmaf(tanh_fast(cc[3] + hc1), vw1, rs[mi * 2 + 1]));
        }

#pragma unroll
    for (int i = 0; i < 4; ++i) {
        rs[i] += __shfl_xor_sync(0xffffffffu, rs[i], 1);
        rs[i] += __shfl_xor_sync(0xffffffffu, rs[i], 2);
    }
    if ((lid & 3) == 0) {
        const size_t r0 = m0 + wm * 32 + (lid >> 2);
        atomicAdd(&g_scores[r0],      rs[0]);
        atomicAdd(&g_scores[r0 + 8],  rs[1]);
        atomicAdd(&g_scores[r0 + 16], rs[2]);
        atomicAdd(&g_scores[r0 + 24], rs[3]);
    }
}

// -------------------- softmax over compacted scores + scatter ----------------
__global__ void softmax_kernel(float* __restrict__ weights) {
    const int b = blockIdx.x;
    const int tid = threadIdx.x;
    const int cnt = g_cnt[b];
    __shared__ float red[256];

    float vals[8];
    float mx = -INFINITY;
#pragma unroll
    for (int i = 0; i < 8; ++i) {
        const int j = tid + i * 256;
        vals[i] = (j < cnt) ? g_scores[b * Sn + j] : -INFINITY;
        mx = fmaxf(mx, vals[i]);
    }
    red[tid] = mx;
    __syncthreads();
    for (int o = 128; o; o >>= 1) {
        if (tid < o) red[tid] = fmaxf(red[tid], red[tid + o]);
        __syncthreads();
    }
    mx = red[0];
    __syncthreads();

    float sum = 0.f;
#pragma unroll
    for (int i = 0; i < 8; ++i) {
        vals[i] = __expf(vals[i] - mx);
        sum += vals[i];
    }
    red[tid] = sum;
    __syncthreads();
    for (int o = 128; o; o >>= 1) {
        if (tid < o) red[tid] += red[tid + o];
        __syncthreads();
    }
    const float inv = 1.0f / red[0];
#pragma unroll
    for (int i = 0; i < 8; ++i) {
        const int j = tid + i * 256;
        if (j < cnt) {
            const float w = vals[i] * inv;
            g_wc[b * Sn + j] = w;
            weights[b * Sn + g_sidx[b * Sn + j]] = w;
        }
    }
}

// -------------------- weighted sum from compact fp16 enc ---------------------
// j-chunks of 128 rows -> 2x blocks for better latency hiding.
__global__ void weighted_kernel(float* __restrict__ out) {
    const int b = blockIdx.y;
    const int cnt = g_cnt[b];
    const int j0 = blockIdx.z * 128;
    if (j0 >= cnt) return;
    const int e2 = blockIdx.x * 256 + threadIdx.x;

    __shared__ float w[128];
    if (threadIdx.x < 128) {
        const int j = j0 + threadIdx.x;
        w[threadIdx.x] = (j < cnt) ? g_wc[b * Sn + j] : 0.0f;
    }
    __syncthreads();

    const __half2* ebase =
        (const __half2*)(g_ench + (size_t)b * Sn * En + (size_t)j0 * En) + e2;
    const int lim = min(128, cnt - j0);
    float ax = 0.f, ay = 0.f;
    for (int t = 0; t < lim; ++t) {
        const float2 v = __half22float2(ebase[(size_t)t * (En / 2)]);
        ax = fmaf(w[t], v.x, ax);
        ay = fmaf(w[t], v.y, ay);
    }
    atomicAdd(&out[b * En + 2 * e2],     ax);
    atomicAdd(&out[b * En + 2 * e2 + 1], ay);
}

// -----------------------------------------------------------------------------
extern "C" void kernel_launch(void* const* d_in, const int* in_sizes, int n_in,
                              void* d_out, int out_size) {
    const float* hidden = (const float*)d_in[0];
    const float* enc    = (const float*)d_in[1];
    const int*   mask   = (const int*)d_in[2];
    const float* Mw     = (const float*)d_in[3];
    const float* Mb     = (const float*)d_in[4];
    const float* Vw     = (const float*)d_in[5];

    float* out_all      = (float*)d_out;
    float* out_weights  = (float*)d_out + Bn * En;

    cudaFuncSetAttribute(scores_mma_kernel,
                         cudaFuncAttributeMaxDynamicSharedMemorySize, SMEM_SC);

    prep_all_kernel<<<64, 256>>>(Mw, mask, out_all);

    dim3 ggrid(Sn / 8, Bn);
    encgather_kernel<<<ggrid, 256>>>(enc);

    scores_mma_kernel<<<Bn * MT * NT, 256, SMEM_SC>>>(hidden, Mb, Vw);

    softmax_kernel<<<Bn, 256>>>(out_weights);

    dim3 wgrid(En / 512, Bn, Sn / 128);
    weighted_kernel<<<wgrid, 256>>>(out_all);
}